// round 8
// baseline (speedup 1.0000x reference)
#include <cuda_runtime.h>
#include <cstdint>

#define UNUM 100000
#define INUM 200000
#define NTOT 300000
#define NNZE 4000000
#define BSZ  4096
#define DIM  64
#define NLAY 3
#define CDIM2 192             // concat store: layers 1..3 only (layer0 read from inputs)
#define EMAX 96               // padded ELL row capacity (mean deg ~12)
#define RPB  128              // rows per combine block
#define NELEM (NTOT * DIM)    // 19,200,000 elems per layer
#define NWORD (NELEM / 32)    // 600,000 mask words per layer

// ---------------- scratch (static device globals; no allocs allowed) ----------------
__device__ __align__(256) float    g_ego [(size_t)NTOT * DIM];       // 76.8 MB
__device__ __align__(256) float    g_side[(size_t)NTOT * DIM];       // 76.8 MB
__device__ __align__(256) float    g_all [(size_t)NTOT * CDIM2];     // 230 MB
__device__ __align__(256) int2     g_ell [(size_t)NTOT * EMAX];      // 230 MB {col, val bits}
__device__ __align__(256) int      g_cnt [NTOT];
__device__ __align__(256) uint32_t g_mask[(size_t)NLAY * NWORD];     // 7.2 MB bit-packed
__device__ float g_acc[2];                                           // bpr_sum, reg_sum

// ---------------- threefry2x32 (exact JAX semantics) ----------------
__host__ __device__ __forceinline__ uint32_t rotl32(uint32_t x, int r) {
    return (x << r) | (x >> (32 - r));
}

__host__ __device__ inline void threefry2x32(uint32_t k0, uint32_t k1,
                                             uint32_t x0, uint32_t x1,
                                             uint32_t &o0, uint32_t &o1) {
    uint32_t k2 = k0 ^ k1 ^ 0x1BD11BDAu;
    x0 += k0; x1 += k1;
#define TF_R(r) { x0 += x1; x1 = rotl32(x1, r); x1 ^= x0; }
    TF_R(13) TF_R(15) TF_R(26) TF_R(6)   x0 += k1; x1 += k2 + 1u;
    TF_R(17) TF_R(29) TF_R(16) TF_R(24)  x0 += k2; x1 += k0 + 2u;
    TF_R(13) TF_R(15) TF_R(26) TF_R(6)   x0 += k0; x1 += k1 + 3u;
    TF_R(17) TF_R(29) TF_R(16) TF_R(24)  x0 += k1; x1 += k2 + 4u;
    TF_R(13) TF_R(15) TF_R(26) TF_R(6)   x0 += k2; x1 += k0 + 5u;
#undef TF_R
    o0 = x0; o1 = x1;
}

// Partitionable (counter-mode) bits: threefry(key, (0, i)), 32-bit finisher o0^o1
__device__ __forceinline__ uint32_t rbits_partitionable(uint32_t k0, uint32_t k1, uint32_t i) {
    uint32_t o0, o1;
    threefry2x32(k0, k1, 0u, i, o0, o1);
    return o0 ^ o1;
}

__device__ __forceinline__ float u01(uint32_t bits) {
    return __uint_as_float((bits >> 9) | 0x3F800000u) - 1.0f;
}

// ---------------- kernels ----------------
// Unified ego init (coalesced copy of both embedding tables) + acc zero.
__global__ void init_kernel(const float* __restrict__ ue, const float* __restrict__ ie) {
    int i = blockIdx.x * blockDim.x + threadIdx.x;
    if (i == 0) { g_acc[0] = 0.f; g_acc[1] = 0.f; }
    if (i >= NTOT * DIM) return;
    g_ego[i] = (i < UNUM * DIM) ? ue[i] : ie[i - UNUM * DIM];
}

// One pass: edge dropout + ELL scatter (dropped edges never stored).
__global__ void scatter_kernel(const float* __restrict__ val, const int* __restrict__ row,
                               const int* __restrict__ col, uint32_t k0, uint32_t k1) {
    int e = blockIdx.x * blockDim.x + threadIdx.x;
    if (e >= NNZE) return;
    float u = u01(rbits_partitionable(k0, k1, (uint32_t)e));
    if (u >= 0.9f) return;                 // dropped: contributes +0 exactly
    float v = val[e] * (1.0f / 0.9f);
    int r = row[e];
    int pos = atomicAdd(&g_cnt[r], 1);
    if (pos < EMAX)
        g_ell[(size_t)r * EMAX + pos] = make_int2(col[e], __float_as_int(v));
}

// Bit-packed message-dropout masks for ALL layers (side stream; overlapped).
__global__ void maskgen_kernel(uint32_t ka0, uint32_t ka1, uint32_t kb0, uint32_t kb1,
                               uint32_t kc0, uint32_t kc1) {
    int t = blockIdx.x * blockDim.x + threadIdx.x;   // elem index within a layer
    if (t >= NELEM) return;
    int lane = threadIdx.x & 31;
    uint32_t k0[3] = {ka0, kb0, kc0}, k1[3] = {ka1, kb1, kc1};
#pragma unroll
    for (int L = 0; L < 3; L++) {
        bool keep = u01(rbits_partitionable(k0[L], k1[L], (uint32_t)t)) < 0.9f;
        uint32_t w = __ballot_sync(0xFFFFFFFFu, keep);
        if (lane == 0) g_mask[(size_t)L * NWORD + (t >> 5)] = w;
    }
}

// Atomic-free SpMM: warp per row; 2 edge-slots x 16 dim-lanes, 2-way unroll (MLP=2).
__global__ void spmm_kernel() {
    int w    = (blockIdx.x * blockDim.x + threadIdx.x) >> 5;
    if (w >= NTOT) return;
    int lane = threadIdx.x & 31;
    int sub  = lane >> 4;       // which edge slot
    int dl   = lane & 15;       // dim quarter (float4)
    int cnt  = g_cnt[w];
    if (cnt > EMAX) cnt = EMAX;
    const int2* ep = g_ell + (size_t)w * EMAX;
    float4 acc = make_float4(0.f, 0.f, 0.f, 0.f);
    int j = sub;
    for (; j + 2 < cnt; j += 4) {          // 2 independent edges in flight
        int2 cva = ep[j];
        int2 cvb = ep[j + 2];
        float4 xa = ((const float4*)(g_ego + (size_t)cva.x * DIM))[dl];
        float4 xb = ((const float4*)(g_ego + (size_t)cvb.x * DIM))[dl];
        float va = __int_as_float(cva.y), vb = __int_as_float(cvb.y);
        acc.x += va * xa.x + vb * xb.x;
        acc.y += va * xa.y + vb * xb.y;
        acc.z += va * xa.z + vb * xb.z;
        acc.w += va * xa.w + vb * xb.w;
    }
    if (j < cnt) {
        int2 cv = ep[j];
        float v = __int_as_float(cv.y);
        float4 x = ((const float4*)(g_ego + (size_t)cv.x * DIM))[dl];
        acc.x += v * x.x; acc.y += v * x.y; acc.z += v * x.z; acc.w += v * x.w;
    }
    acc.x += __shfl_xor_sync(0xFFFFFFFFu, acc.x, 16);
    acc.y += __shfl_xor_sync(0xFFFFFFFFu, acc.y, 16);
    acc.z += __shfl_xor_sync(0xFFFFFFFFu, acc.z, 16);
    acc.w += __shfl_xor_sync(0xFFFFFFFFu, acc.w, 16);
    if (sub == 0)
        ((float4*)(g_side + (size_t)w * DIM))[dl] = acc;
}

// side@Wg + b_gc + (ego*side)@Wb + b_bi -> leaky_relu -> g_ego (in place)
// Exact R4 geometry (measured 218 us): 256 thr, 128 rows/block, 2 rows x 16 cols.
__global__ void __launch_bounds__(256, 2)
combine_kernel(const float* __restrict__ Wg, const float* __restrict__ bg,
               const float* __restrict__ Wb, const float* __restrict__ bb) {
    extern __shared__ float sm[];
    float* sWg = sm;                      // 4096
    float* sWb = sm + 4096;               // 4096
    float* sS  = sm + 8192;               // 2 planes x 64 x 65
    float* sE  = sS + 2 * 64 * 65;        // 2 planes x 64 x 65
    const int PL = 64 * 65;
    int tid  = threadIdx.x;
    int row0 = blockIdx.x * RPB;

    for (int i = tid; i < 4096; i += 256) { sWg[i] = Wg[i]; sWb[i] = Wb[i]; }
    for (int i = tid; i < RPB * 16; i += 256) {     // float4 granularity
        int r = i >> 4, q = i & 15;
        int gr = row0 + r;
        float4 s = make_float4(0.f, 0.f, 0.f, 0.f), e = s;
        if (gr < NTOT) {
            s = ((const float4*)(g_side + (size_t)gr * DIM))[q];
            e = ((const float4*)(g_ego  + (size_t)gr * DIM))[q];
        }
        int p = r & 1, rp = r >> 1;
        float* ds = &sS[p * PL + rp * 65 + q * 4];
        float* de = &sE[p * PL + rp * 65 + q * 4];
        ds[0] = s.x; ds[1] = s.y; ds[2] = s.z; ds[3] = s.w;
        de[0] = e.x; de[1] = e.y; de[2] = e.z; de[3] = e.w;
    }
    __syncthreads();

    int cg = tid >> 6;           // 0..3 column group (warp-uniform)
    int rp = tid & 63;           // row pair
    int c0 = cg * 16;
    float acc0[16], acc1[16];
#pragma unroll
    for (int c = 0; c < 16; c++) {
        float b = bg[c0 + c] + bb[c0 + c];
        acc0[c] = b; acc1[c] = b;
    }

    for (int j = 0; j < 64; j++) {
        float s0 = sS[rp * 65 + j];
        float s1 = sS[PL + rp * 65 + j];
        float es0 = sE[rp * 65 + j] * s0;
        float es1 = sE[PL + rp * 65 + j] * s1;
        const float4* wg4 = (const float4*)&sWg[j * 64 + c0];
        const float4* wb4 = (const float4*)&sWb[j * 64 + c0];
#pragma unroll
        for (int q = 0; q < 4; q++) {
            float4 wg = wg4[q], wb = wb4[q];
            acc0[4*q+0] += s0 * wg.x + es0 * wb.x;
            acc0[4*q+1] += s0 * wg.y + es0 * wb.y;
            acc0[4*q+2] += s0 * wg.z + es0 * wb.z;
            acc0[4*q+3] += s0 * wg.w + es0 * wb.w;
            acc1[4*q+0] += s1 * wg.x + es1 * wb.x;
            acc1[4*q+1] += s1 * wg.y + es1 * wb.y;
            acc1[4*q+2] += s1 * wg.z + es1 * wb.z;
            acc1[4*q+3] += s1 * wg.w + es1 * wb.w;
        }
    }

#pragma unroll
    for (int p = 0; p < 2; p++) {
        int gr = row0 + rp * 2 + p;
        if (gr >= NTOT) continue;
        float* accp = p ? acc1 : acc0;
        float4* dst = (float4*)(g_ego + (size_t)gr * DIM + c0);
#pragma unroll
        for (int q = 0; q < 4; q++) {
            float a = accp[4*q+0], b = accp[4*q+1], c2 = accp[4*q+2], d = accp[4*q+3];
            a  = (a  >= 0.f) ? a  : 0.2f * a;
            b  = (b  >= 0.f) ? b  : 0.2f * b;
            c2 = (c2 >= 0.f) ? c2 : 0.2f * c2;
            d  = (d  >= 0.f) ? d  : 0.2f * d;
            dst[q] = make_float4(a, b, c2, d);
        }
    }
}

// Msg dropout (precomputed bitmask) + row L2 normalize. Warp per row.
// Dropped un-normalized ego -> g_ego (skipped on last layer), normalized -> g_all.
__global__ void msgnorm_kernel(int layer, int write_ego) {
    int w    = (blockIdx.x * blockDim.x + threadIdx.x) >> 5;
    int lane = threadIdx.x & 31;
    if (w >= NTOT) return;
    size_t base = (size_t)w * DIM;
    float2 v = ((const float2*)(g_ego + base))[lane];
    uint32_t mw = g_mask[(size_t)layer * NWORD + w * 2 + (lane >> 4)];
    int sh = (lane * 2) & 31;
    v.x = ((mw >> sh) & 1u)       ? v.x * (1.0f / 0.9f) : 0.f;
    v.y = ((mw >> (sh + 1)) & 1u) ? v.y * (1.0f / 0.9f) : 0.f;
    if (write_ego)
        ((float2*)(g_ego + base))[lane] = v;

    float ss = v.x * v.x + v.y * v.y;
#pragma unroll
    for (int o = 16; o; o >>= 1) ss += __shfl_xor_sync(0xFFFFFFFFu, ss, o);
    float inv = 1.0f / fmaxf(sqrtf(ss), 1e-12f);
    float* dst = g_all + (size_t)w * CDIM2 + (size_t)layer * DIM;
    ((float2*)dst)[lane] = make_float2(v.x * inv, v.y * inv);
}

// warp per sample: BPR + reg partial sums. Concat = [raw emb | g_all(192)].
__global__ void loss_kernel(const float* __restrict__ ue0, const float* __restrict__ ie0,
                            const int* __restrict__ uid, const int* __restrict__ pid,
                            const int* __restrict__ nid) {
    int w    = (blockIdx.x * blockDim.x + threadIdx.x) >> 5;
    int lane = threadIdx.x & 31;
    if (w >= BSZ) return;
    int u = uid[w], p = pid[w], n = nid[w];
    const float* au = (lane < 8) ? ue0 + (size_t)u * DIM + lane * 8
                                 : g_all + (size_t)u * CDIM2 + lane * 8 - 64;
    const float* bp = (lane < 8) ? ie0 + (size_t)p * DIM + lane * 8
                                 : g_all + (size_t)(UNUM + p) * CDIM2 + lane * 8 - 64;
    const float* bn = (lane < 8) ? ie0 + (size_t)n * DIM + lane * 8
                                 : g_all + (size_t)(UNUM + n) * CDIM2 + lane * 8 - 64;
    float pos = 0.f, neg = 0.f;
#pragma unroll
    for (int t = 0; t < 2; t++) {
        float4 a = ((const float4*)au)[t];
        float4 b = ((const float4*)bp)[t];
        float4 c = ((const float4*)bn)[t];
        pos += a.x * b.x + a.y * b.y + a.z * b.z + a.w * b.w;
        neg += a.x * c.x + a.y * c.y + a.z * c.z + a.w * c.w;
    }
    float2 a0 = ((const float2*)(ue0 + (size_t)u * DIM))[lane];
    float2 b0 = ((const float2*)(ie0 + (size_t)p * DIM))[lane];
    float2 c0 = ((const float2*)(ie0 + (size_t)n * DIM))[lane];
    float rg = a0.x * a0.x + a0.y * a0.y + b0.x * b0.x + b0.y * b0.y + c0.x * c0.x + c0.y * c0.y;
#pragma unroll
    for (int o = 16; o; o >>= 1) {
        pos += __shfl_xor_sync(0xFFFFFFFFu, pos, o);
        neg += __shfl_xor_sync(0xFFFFFFFFu, neg, o);
        rg  += __shfl_xor_sync(0xFFFFFFFFu, rg,  o);
    }
    if (lane == 0) {
        float x = pos - neg;
        float ls = fminf(x, 0.f) - log1pf(expf(-fabsf(x)));  // stable log_sigmoid
        atomicAdd(&g_acc[0], ls);
        atomicAdd(&g_acc[1], rg);
    }
}

__global__ void fin_kernel(float* out, int osz) {
    float bpr = -g_acc[0] / (float)BSZ;
    float reg = 1e-4f * 0.5f * g_acc[1] / (float)BSZ;
    if (osz >= 3) { out[0] = bpr + reg; out[1] = bpr; out[2] = reg; }
    else          { out[0] = bpr + reg; }
}

// ---------------- launch ----------------
extern "C" void kernel_launch(void* const* d_in, const int* in_sizes, int n_in,
                              void* d_out, int out_size) {
    const float* user_emb = (const float*)d_in[0];
    const float* item_emb = (const float*)d_in[1];
    const float* W_gc     = (const float*)d_in[2];
    const float* b_gc     = (const float*)d_in[3];
    const float* W_bi     = (const float*)d_in[4];
    const float* b_bi     = (const float*)d_in[5];
    const float* val      = (const float*)d_in[6];
    const int*   row      = (const int*)d_in[7];
    const int*   col      = (const int*)d_in[8];
    const int*   uid      = (const int*)d_in[9];
    const int*   pid      = (const int*)d_in[10];
    const int*   nid      = (const int*)d_in[11];

    // derived threefry keys: base key = (0, 42); fold_in(d) = threefry(key, (0, d))
    uint32_t ke0, ke1;
    threefry2x32(0u, 42u, 0u, 0u, ke0, ke1);
    uint32_t mk0[NLAY], mk1[NLAY];
    for (int k = 0; k < NLAY; k++)
        threefry2x32(0u, 42u, 0u, (uint32_t)(k + 1), mk0[k], mk1[k]);

    const size_t SMEM = (8192 + 4 * 64 * 65) * sizeof(float);   // ~99.3 KB

    static cudaStream_t s_side = nullptr;
    static cudaEvent_t ev_fork = nullptr, ev_join = nullptr;
    if (s_side == nullptr) {
        cudaFuncSetAttribute(combine_kernel, cudaFuncAttributeMaxDynamicSharedMemorySize, (int)SMEM);
        cudaStreamCreateWithFlags(&s_side, cudaStreamNonBlocking);
        cudaEventCreateWithFlags(&ev_fork, cudaEventDisableTiming);
        cudaEventCreateWithFlags(&ev_join, cudaEventDisableTiming);
    }

    void* cnt_ptr = nullptr;
    cudaGetSymbolAddress(&cnt_ptr, g_cnt);

    cudaMemsetAsync(cnt_ptr, 0, NTOT * sizeof(int));
    init_kernel<<<(NTOT * DIM + 255) / 256, 256>>>(user_emb, item_emb);

    // fork: side stream generates all 3 layers' dropout masks; first consumer is
    // msgnorm_0 at ~scatter+spmm0+combine0 into the graph -> ample slack.
    cudaEventRecord(ev_fork, 0);
    cudaStreamWaitEvent(s_side, ev_fork, 0);
    maskgen_kernel<<<(NELEM + 255) / 256, 256, 0, s_side>>>(
        mk0[0], mk1[0], mk0[1], mk1[1], mk0[2], mk1[2]);
    cudaEventRecord(ev_join, s_side);

    scatter_kernel<<<(NNZE + 255) / 256, 256>>>(val, row, col, ke0, ke1);

    for (int k = 0; k < NLAY; k++) {
        spmm_kernel<<<(NTOT * 32 + 255) / 256, 256>>>();
        combine_kernel<<<(NTOT + RPB - 1) / RPB, 256, SMEM>>>(
            W_gc + k * 4096, b_gc + k * 64, W_bi + k * 4096, b_bi + k * 64);
        if (k == 0) cudaStreamWaitEvent(0, ev_join, 0);   // masks ready before msgnorm_0
        msgnorm_kernel<<<(NTOT * 32 + 255) / 256, 256>>>(k, (k != NLAY - 1) ? 1 : 0);
    }

    loss_kernel<<<(BSZ * 32 + 255) / 256, 256>>>(user_emb, item_emb, uid, pid, nid);
    fin_kernel<<<1, 1>>>((float*)d_out, out_size);
}

// round 9
// speedup vs baseline: 1.0926x; 1.0926x over previous
#include <cuda_runtime.h>
#include <cstdint>

#define UNUM 100000
#define INUM 200000
#define NTOT 300000
#define NNZE 4000000
#define BSZ  4096
#define DIM  64
#define NLAY 3
#define CDIM2 192             // concat store: layers 1..3 only (layer0 read from inputs)
#define EMAX 96               // padded ELL row capacity (mean deg ~12)
#define RPB  128              // rows per combine block
#define NELEM (NTOT * DIM)    // 19,200,000 elems per layer
#define NWORD (NELEM / 32)    // 600,000 mask words per layer

// ---------------- scratch (static device globals; no allocs allowed) ----------------
__device__ __align__(256) float    g_ego [(size_t)NTOT * DIM];       // 76.8 MB
__device__ __align__(256) float    g_side[(size_t)NTOT * DIM];       // 76.8 MB
__device__ __align__(256) float    g_all [(size_t)NTOT * CDIM2];     // 230 MB
__device__ __align__(256) int2     g_ell [(size_t)NTOT * EMAX];      // 230 MB {col, val bits}
__device__ __align__(256) int      g_cnt [NTOT];
__device__ __align__(256) uint32_t g_mask[(size_t)NLAY * NWORD];     // 7.2 MB bit-packed
__device__ float g_acc[2];                                           // bpr_sum, reg_sum

// ---------------- threefry2x32 (exact JAX semantics) ----------------
__host__ __device__ __forceinline__ uint32_t rotl32(uint32_t x, int r) {
    return (x << r) | (x >> (32 - r));
}

__host__ __device__ inline void threefry2x32(uint32_t k0, uint32_t k1,
                                             uint32_t x0, uint32_t x1,
                                             uint32_t &o0, uint32_t &o1) {
    uint32_t k2 = k0 ^ k1 ^ 0x1BD11BDAu;
    x0 += k0; x1 += k1;
#define TF_R(r) { x0 += x1; x1 = rotl32(x1, r); x1 ^= x0; }
    TF_R(13) TF_R(15) TF_R(26) TF_R(6)   x0 += k1; x1 += k2 + 1u;
    TF_R(17) TF_R(29) TF_R(16) TF_R(24)  x0 += k2; x1 += k0 + 2u;
    TF_R(13) TF_R(15) TF_R(26) TF_R(6)   x0 += k0; x1 += k1 + 3u;
    TF_R(17) TF_R(29) TF_R(16) TF_R(24)  x0 += k1; x1 += k2 + 4u;
    TF_R(13) TF_R(15) TF_R(26) TF_R(6)   x0 += k2; x1 += k0 + 5u;
#undef TF_R
    o0 = x0; o1 = x1;
}

// Partitionable (counter-mode) bits: threefry(key, (0, i)), 32-bit finisher o0^o1
__device__ __forceinline__ uint32_t rbits_partitionable(uint32_t k0, uint32_t k1, uint32_t i) {
    uint32_t o0, o1;
    threefry2x32(k0, k1, 0u, i, o0, o1);
    return o0 ^ o1;
}

__device__ __forceinline__ float u01(uint32_t bits) {
    return __uint_as_float((bits >> 9) | 0x3F800000u) - 1.0f;
}

// ---------------- kernels ----------------
// Unified ego init (coalesced copy of both embedding tables) + acc zero.
__global__ void init_kernel(const float* __restrict__ ue, const float* __restrict__ ie) {
    int i = blockIdx.x * blockDim.x + threadIdx.x;
    if (i == 0) { g_acc[0] = 0.f; g_acc[1] = 0.f; }
    if (i >= NTOT * DIM) return;
    g_ego[i] = (i < UNUM * DIM) ? ue[i] : ie[i - UNUM * DIM];
}

// One pass: edge dropout + ELL scatter (dropped edges never stored).
__global__ void scatter_kernel(const float* __restrict__ val, const int* __restrict__ row,
                               const int* __restrict__ col, uint32_t k0, uint32_t k1) {
    int e = blockIdx.x * blockDim.x + threadIdx.x;
    if (e >= NNZE) return;
    float u = u01(rbits_partitionable(k0, k1, (uint32_t)e));
    if (u >= 0.9f) return;                 // dropped: contributes +0 exactly
    float v = val[e] * (1.0f / 0.9f);
    int r = row[e];
    int pos = atomicAdd(&g_cnt[r], 1);
    if (pos < EMAX)
        g_ell[(size_t)r * EMAX + pos] = make_int2(col[e], __float_as_int(v));
}

// Atomic-free SpMM: warp per row; 2 edge-slots x 16 dim-lanes, 2-way unroll (MLP=2).
// ALSO generates this layer's dropout mask words for its row (2 threefry/lane),
// hidden in the gather-stall issue slots (measured issue=25.7% before).
__global__ void spmm_kernel(uint32_t mk0, uint32_t mk1, int layer) {
    int w    = (blockIdx.x * blockDim.x + threadIdx.x) >> 5;
    if (w >= NTOT) return;
    int lane = threadIdx.x & 31;
    int sub  = lane >> 4;       // which edge slot
    int dl   = lane & 15;       // dim quarter (float4)
    int cnt  = g_cnt[w];
    if (cnt > EMAX) cnt = EMAX;
    const int2* ep = g_ell + (size_t)w * EMAX;

    // ---- mask generation for row w (words 2w, 2w+1 of this layer) ----
    uint32_t eb = (uint32_t)w * 64u + (uint32_t)lane;
    bool keep0 = u01(rbits_partitionable(mk0, mk1, eb))        < 0.9f;
    bool keep1 = u01(rbits_partitionable(mk0, mk1, eb + 32u))  < 0.9f;
    uint32_t w0 = __ballot_sync(0xFFFFFFFFu, keep0);
    uint32_t w1 = __ballot_sync(0xFFFFFFFFu, keep1);
    if (lane == 0) {
        g_mask[(size_t)layer * NWORD + w * 2]     = w0;
        g_mask[(size_t)layer * NWORD + w * 2 + 1] = w1;
    }

    // ---- gather ----
    float4 acc = make_float4(0.f, 0.f, 0.f, 0.f);
    int j = sub;
    for (; j + 2 < cnt; j += 4) {          // 2 independent edges in flight
        int2 cva = ep[j];
        int2 cvb = ep[j + 2];
        float4 xa = ((const float4*)(g_ego + (size_t)cva.x * DIM))[dl];
        float4 xb = ((const float4*)(g_ego + (size_t)cvb.x * DIM))[dl];
        float va = __int_as_float(cva.y), vb = __int_as_float(cvb.y);
        acc.x += va * xa.x + vb * xb.x;
        acc.y += va * xa.y + vb * xb.y;
        acc.z += va * xa.z + vb * xb.z;
        acc.w += va * xa.w + vb * xb.w;
    }
    if (j < cnt) {
        int2 cv = ep[j];
        float v = __int_as_float(cv.y);
        float4 x = ((const float4*)(g_ego + (size_t)cv.x * DIM))[dl];
        acc.x += v * x.x; acc.y += v * x.y; acc.z += v * x.z; acc.w += v * x.w;
    }
    acc.x += __shfl_xor_sync(0xFFFFFFFFu, acc.x, 16);
    acc.y += __shfl_xor_sync(0xFFFFFFFFu, acc.y, 16);
    acc.z += __shfl_xor_sync(0xFFFFFFFFu, acc.z, 16);
    acc.w += __shfl_xor_sync(0xFFFFFFFFu, acc.w, 16);
    if (sub == 0)
        ((float4*)(g_side + (size_t)w * DIM))[dl] = acc;
}

// side@Wg + b_gc + (ego*side)@Wb + b_bi -> leaky_relu -> g_ego (in place)
// Exact R4 geometry (measured 218 us): 256 thr, 128 rows/block, 2 rows x 16 cols.
__global__ void __launch_bounds__(256, 2)
combine_kernel(const float* __restrict__ Wg, const float* __restrict__ bg,
               const float* __restrict__ Wb, const float* __restrict__ bb) {
    extern __shared__ float sm[];
    float* sWg = sm;                      // 4096
    float* sWb = sm + 4096;               // 4096
    float* sS  = sm + 8192;               // 2 planes x 64 x 65
    float* sE  = sS + 2 * 64 * 65;        // 2 planes x 64 x 65
    const int PL = 64 * 65;
    int tid  = threadIdx.x;
    int row0 = blockIdx.x * RPB;

    for (int i = tid; i < 4096; i += 256) { sWg[i] = Wg[i]; sWb[i] = Wb[i]; }
    for (int i = tid; i < RPB * 16; i += 256) {     // float4 granularity
        int r = i >> 4, q = i & 15;
        int gr = row0 + r;
        float4 s = make_float4(0.f, 0.f, 0.f, 0.f), e = s;
        if (gr < NTOT) {
            s = ((const float4*)(g_side + (size_t)gr * DIM))[q];
            e = ((const float4*)(g_ego  + (size_t)gr * DIM))[q];
        }
        int p = r & 1, rp = r >> 1;
        float* ds = &sS[p * PL + rp * 65 + q * 4];
        float* de = &sE[p * PL + rp * 65 + q * 4];
        ds[0] = s.x; ds[1] = s.y; ds[2] = s.z; ds[3] = s.w;
        de[0] = e.x; de[1] = e.y; de[2] = e.z; de[3] = e.w;
    }
    __syncthreads();

    int cg = tid >> 6;           // 0..3 column group (warp-uniform)
    int rp = tid & 63;           // row pair
    int c0 = cg * 16;
    float acc0[16], acc1[16];
#pragma unroll
    for (int c = 0; c < 16; c++) {
        float b = bg[c0 + c] + bb[c0 + c];
        acc0[c] = b; acc1[c] = b;
    }

    for (int j = 0; j < 64; j++) {
        float s0 = sS[rp * 65 + j];
        float s1 = sS[PL + rp * 65 + j];
        float es0 = sE[rp * 65 + j] * s0;
        float es1 = sE[PL + rp * 65 + j] * s1;
        const float4* wg4 = (const float4*)&sWg[j * 64 + c0];
        const float4* wb4 = (const float4*)&sWb[j * 64 + c0];
#pragma unroll
        for (int q = 0; q < 4; q++) {
            float4 wg = wg4[q], wb = wb4[q];
            acc0[4*q+0] += s0 * wg.x + es0 * wb.x;
            acc0[4*q+1] += s0 * wg.y + es0 * wb.y;
            acc0[4*q+2] += s0 * wg.z + es0 * wb.z;
            acc0[4*q+3] += s0 * wg.w + es0 * wb.w;
            acc1[4*q+0] += s1 * wg.x + es1 * wb.x;
            acc1[4*q+1] += s1 * wg.y + es1 * wb.y;
            acc1[4*q+2] += s1 * wg.z + es1 * wb.z;
            acc1[4*q+3] += s1 * wg.w + es1 * wb.w;
        }
    }

#pragma unroll
    for (int p = 0; p < 2; p++) {
        int gr = row0 + rp * 2 + p;
        if (gr >= NTOT) continue;
        float* accp = p ? acc1 : acc0;
        float4* dst = (float4*)(g_ego + (size_t)gr * DIM + c0);
#pragma unroll
        for (int q = 0; q < 4; q++) {
            float a = accp[4*q+0], b = accp[4*q+1], c2 = accp[4*q+2], d = accp[4*q+3];
            a  = (a  >= 0.f) ? a  : 0.2f * a;
            b  = (b  >= 0.f) ? b  : 0.2f * b;
            c2 = (c2 >= 0.f) ? c2 : 0.2f * c2;
            d  = (d  >= 0.f) ? d  : 0.2f * d;
            dst[q] = make_float4(a, b, c2, d);
        }
    }
}

// Msg dropout (precomputed bitmask) + row L2 normalize. Warp per row.
// Dropped un-normalized ego -> g_ego (skipped on last layer), normalized -> g_all.
__global__ void msgnorm_kernel(int layer, int write_ego) {
    int w    = (blockIdx.x * blockDim.x + threadIdx.x) >> 5;
    int lane = threadIdx.x & 31;
    if (w >= NTOT) return;
    size_t base = (size_t)w * DIM;
    float2 v = ((const float2*)(g_ego + base))[lane];
    uint32_t mw = g_mask[(size_t)layer * NWORD + w * 2 + (lane >> 4)];
    int sh = (lane * 2) & 31;
    v.x = ((mw >> sh) & 1u)       ? v.x * (1.0f / 0.9f) : 0.f;
    v.y = ((mw >> (sh + 1)) & 1u) ? v.y * (1.0f / 0.9f) : 0.f;
    if (write_ego)
        ((float2*)(g_ego + base))[lane] = v;

    float ss = v.x * v.x + v.y * v.y;
#pragma unroll
    for (int o = 16; o; o >>= 1) ss += __shfl_xor_sync(0xFFFFFFFFu, ss, o);
    float inv = 1.0f / fmaxf(sqrtf(ss), 1e-12f);
    float* dst = g_all + (size_t)w * CDIM2 + (size_t)layer * DIM;
    ((float2*)dst)[lane] = make_float2(v.x * inv, v.y * inv);
}

// warp per sample: BPR + reg partial sums. Concat = [raw emb | g_all(192)].
__global__ void loss_kernel(const float* __restrict__ ue0, const float* __restrict__ ie0,
                            const int* __restrict__ uid, const int* __restrict__ pid,
                            const int* __restrict__ nid) {
    int w    = (blockIdx.x * blockDim.x + threadIdx.x) >> 5;
    int lane = threadIdx.x & 31;
    if (w >= BSZ) return;
    int u = uid[w], p = pid[w], n = nid[w];
    const float* au = (lane < 8) ? ue0 + (size_t)u * DIM + lane * 8
                                 : g_all + (size_t)u * CDIM2 + lane * 8 - 64;
    const float* bp = (lane < 8) ? ie0 + (size_t)p * DIM + lane * 8
                                 : g_all + (size_t)(UNUM + p) * CDIM2 + lane * 8 - 64;
    const float* bn = (lane < 8) ? ie0 + (size_t)n * DIM + lane * 8
                                 : g_all + (size_t)(UNUM + n) * CDIM2 + lane * 8 - 64;
    float pos = 0.f, neg = 0.f;
#pragma unroll
    for (int t = 0; t < 2; t++) {
        float4 a = ((const float4*)au)[t];
        float4 b = ((const float4*)bp)[t];
        float4 c = ((const float4*)bn)[t];
        pos += a.x * b.x + a.y * b.y + a.z * b.z + a.w * b.w;
        neg += a.x * c.x + a.y * c.y + a.z * c.z + a.w * c.w;
    }
    float2 a0 = ((const float2*)(ue0 + (size_t)u * DIM))[lane];
    float2 b0 = ((const float2*)(ie0 + (size_t)p * DIM))[lane];
    float2 c0 = ((const float2*)(ie0 + (size_t)n * DIM))[lane];
    float rg = a0.x * a0.x + a0.y * a0.y + b0.x * b0.x + b0.y * b0.y + c0.x * c0.x + c0.y * c0.y;
#pragma unroll
    for (int o = 16; o; o >>= 1) {
        pos += __shfl_xor_sync(0xFFFFFFFFu, pos, o);
        neg += __shfl_xor_sync(0xFFFFFFFFu, neg, o);
        rg  += __shfl_xor_sync(0xFFFFFFFFu, rg,  o);
    }
    if (lane == 0) {
        float x = pos - neg;
        float ls = fminf(x, 0.f) - log1pf(expf(-fabsf(x)));  // stable log_sigmoid
        atomicAdd(&g_acc[0], ls);
        atomicAdd(&g_acc[1], rg);
    }
}

__global__ void fin_kernel(float* out, int osz) {
    float bpr = -g_acc[0] / (float)BSZ;
    float reg = 1e-4f * 0.5f * g_acc[1] / (float)BSZ;
    if (osz >= 3) { out[0] = bpr + reg; out[1] = bpr; out[2] = reg; }
    else          { out[0] = bpr + reg; }
}

// ---------------- launch ----------------
extern "C" void kernel_launch(void* const* d_in, const int* in_sizes, int n_in,
                              void* d_out, int out_size) {
    const float* user_emb = (const float*)d_in[0];
    const float* item_emb = (const float*)d_in[1];
    const float* W_gc     = (const float*)d_in[2];
    const float* b_gc     = (const float*)d_in[3];
    const float* W_bi     = (const float*)d_in[4];
    const float* b_bi     = (const float*)d_in[5];
    const float* val      = (const float*)d_in[6];
    const int*   row      = (const int*)d_in[7];
    const int*   col      = (const int*)d_in[8];
    const int*   uid      = (const int*)d_in[9];
    const int*   pid      = (const int*)d_in[10];
    const int*   nid      = (const int*)d_in[11];

    // derived threefry keys: base key = (0, 42); fold_in(d) = threefry(key, (0, d))
    uint32_t ke0, ke1;
    threefry2x32(0u, 42u, 0u, 0u, ke0, ke1);
    uint32_t mk0[NLAY], mk1[NLAY];
    for (int k = 0; k < NLAY; k++)
        threefry2x32(0u, 42u, 0u, (uint32_t)(k + 1), mk0[k], mk1[k]);

    const size_t SMEM = (8192 + 4 * 64 * 65) * sizeof(float);   // ~99.3 KB
    static bool attr_set = false;
    if (!attr_set) {
        cudaFuncSetAttribute(combine_kernel, cudaFuncAttributeMaxDynamicSharedMemorySize, (int)SMEM);
        attr_set = true;
    }

    void* cnt_ptr = nullptr;
    cudaGetSymbolAddress(&cnt_ptr, g_cnt);

    cudaMemsetAsync(cnt_ptr, 0, NTOT * sizeof(int));
    init_kernel<<<(NTOT * DIM + 255) / 256, 256>>>(user_emb, item_emb);
    scatter_kernel<<<(NNZE + 255) / 256, 256>>>(val, row, col, ke0, ke1);

    for (int k = 0; k < NLAY; k++) {
        spmm_kernel<<<(NTOT * 32 + 255) / 256, 256>>>(mk0[k], mk1[k], k);
        combine_kernel<<<(NTOT + RPB - 1) / RPB, 256, SMEM>>>(
            W_gc + k * 4096, b_gc + k * 64, W_bi + k * 4096, b_bi + k * 64);
        msgnorm_kernel<<<(NTOT * 32 + 255) / 256, 256>>>(k, (k != NLAY - 1) ? 1 : 0);
    }

    loss_kernel<<<(BSZ * 32 + 255) / 256, 256>>>(user_emb, item_emb, uid, pid, nid);
    fin_kernel<<<1, 1>>>((float*)d_out, out_size);
}

// round 10
// speedup vs baseline: 1.5359x; 1.4058x over previous
#include <cuda_runtime.h>
#include <cstdint>

#define UNUM 100000
#define INUM 200000
#define NTOT 300000
#define NNZE 4000000
#define BSZ  4096
#define DIM  64
#define NLAY 3
#define CDIM2 192             // concat store: layers 1..3 only (layer0 read from inputs)
#define EMAX 96               // padded ELL row capacity (mean deg ~12)
#define RPB  128              // rows per combine block
#define NELEM (NTOT * DIM)    // 19,200,000 elems per layer
#define NWORD (NELEM / 32)    // 600,000 mask words per layer

#define A_STRIDE 132          // words; %32==4 -> conflict-free A frag loads
#define B_STRIDE 72           // words; %32==8 -> conflict-free B frag loads

// ---------------- scratch (static device globals; no allocs allowed) ----------------
__device__ __align__(256) float    g_ego [(size_t)NTOT * DIM];       // 76.8 MB
__device__ __align__(256) float    g_side[(size_t)NTOT * DIM];       // 76.8 MB
__device__ __align__(256) float    g_all [(size_t)NTOT * CDIM2];     // 230 MB
__device__ __align__(256) int2     g_ell [(size_t)NTOT * EMAX];      // 230 MB {col, val bits}
__device__ __align__(256) int      g_cnt [NTOT];
__device__ __align__(256) uint32_t g_mask[(size_t)NLAY * NWORD];     // 7.2 MB bit-packed
__device__ float g_acc[2];                                           // bpr_sum, reg_sum

// ---------------- threefry2x32 (exact JAX semantics) ----------------
__host__ __device__ __forceinline__ uint32_t rotl32(uint32_t x, int r) {
    return (x << r) | (x >> (32 - r));
}

__host__ __device__ inline void threefry2x32(uint32_t k0, uint32_t k1,
                                             uint32_t x0, uint32_t x1,
                                             uint32_t &o0, uint32_t &o1) {
    uint32_t k2 = k0 ^ k1 ^ 0x1BD11BDAu;
    x0 += k0; x1 += k1;
#define TF_R(r) { x0 += x1; x1 = rotl32(x1, r); x1 ^= x0; }
    TF_R(13) TF_R(15) TF_R(26) TF_R(6)   x0 += k1; x1 += k2 + 1u;
    TF_R(17) TF_R(29) TF_R(16) TF_R(24)  x0 += k2; x1 += k0 + 2u;
    TF_R(13) TF_R(15) TF_R(26) TF_R(6)   x0 += k0; x1 += k1 + 3u;
    TF_R(17) TF_R(29) TF_R(16) TF_R(24)  x0 += k1; x1 += k2 + 4u;
    TF_R(13) TF_R(15) TF_R(26) TF_R(6)   x0 += k2; x1 += k0 + 5u;
#undef TF_R
    o0 = x0; o1 = x1;
}

// Partitionable (counter-mode) bits: threefry(key, (0, i)), 32-bit finisher o0^o1
__device__ __forceinline__ uint32_t rbits_partitionable(uint32_t k0, uint32_t k1, uint32_t i) {
    uint32_t o0, o1;
    threefry2x32(k0, k1, 0u, i, o0, o1);
    return o0 ^ o1;
}

__device__ __forceinline__ float u01(uint32_t bits) {
    return __uint_as_float((bits >> 9) | 0x3F800000u) - 1.0f;
}

__device__ __forceinline__ uint32_t f2tf32(float x) {
    uint32_t r;
    asm("cvt.rna.tf32.f32 %0, %1;" : "=r"(r) : "f"(x));
    return r;
}

__device__ __forceinline__ void mma_tf32(float c[4], uint32_t a0, uint32_t a1,
                                         uint32_t a2, uint32_t a3,
                                         uint32_t b0, uint32_t b1) {
    asm volatile(
        "mma.sync.aligned.m16n8k8.row.col.f32.tf32.tf32.f32 "
        "{%0,%1,%2,%3}, {%4,%5,%6,%7}, {%8,%9}, {%0,%1,%2,%3};\n"
        : "+f"(c[0]), "+f"(c[1]), "+f"(c[2]), "+f"(c[3])
        : "r"(a0), "r"(a1), "r"(a2), "r"(a3), "r"(b0), "r"(b1));
}

// ---------------- kernels ----------------
// Unified ego init (coalesced copy of both embedding tables) + acc zero.
__global__ void init_kernel(const float* __restrict__ ue, const float* __restrict__ ie) {
    int i = blockIdx.x * blockDim.x + threadIdx.x;
    if (i == 0) { g_acc[0] = 0.f; g_acc[1] = 0.f; }
    if (i >= NTOT * DIM) return;
    g_ego[i] = (i < UNUM * DIM) ? ue[i] : ie[i - UNUM * DIM];
}

// One pass: edge dropout + ELL scatter (dropped edges never stored).
__global__ void scatter_kernel(const float* __restrict__ val, const int* __restrict__ row,
                               const int* __restrict__ col, uint32_t k0, uint32_t k1) {
    int e = blockIdx.x * blockDim.x + threadIdx.x;
    if (e >= NNZE) return;
    float u = u01(rbits_partitionable(k0, k1, (uint32_t)e));
    if (u >= 0.9f) return;                 // dropped: contributes +0 exactly
    float v = val[e] * (1.0f / 0.9f);
    int r = row[e];
    int pos = atomicAdd(&g_cnt[r], 1);
    if (pos < EMAX)
        g_ell[(size_t)r * EMAX + pos] = make_int2(col[e], __float_as_int(v));
}

// Atomic-free SpMM: warp per row; 2 edge-slots x 16 dim-lanes, 2-way unroll (MLP=2).
// ALSO generates this layer's dropout mask words (hidden in gather-stall slots).
__global__ void spmm_kernel(uint32_t mk0, uint32_t mk1, int layer) {
    int w    = (blockIdx.x * blockDim.x + threadIdx.x) >> 5;
    if (w >= NTOT) return;
    int lane = threadIdx.x & 31;
    int sub  = lane >> 4;       // which edge slot
    int dl   = lane & 15;       // dim quarter (float4)
    int cnt  = g_cnt[w];
    if (cnt > EMAX) cnt = EMAX;
    const int2* ep = g_ell + (size_t)w * EMAX;

    // ---- mask generation for row w (words 2w, 2w+1 of this layer) ----
    uint32_t eb = (uint32_t)w * 64u + (uint32_t)lane;
    bool keep0 = u01(rbits_partitionable(mk0, mk1, eb))       < 0.9f;
    bool keep1 = u01(rbits_partitionable(mk0, mk1, eb + 32u)) < 0.9f;
    uint32_t w0 = __ballot_sync(0xFFFFFFFFu, keep0);
    uint32_t w1 = __ballot_sync(0xFFFFFFFFu, keep1);
    if (lane == 0) {
        g_mask[(size_t)layer * NWORD + w * 2]     = w0;
        g_mask[(size_t)layer * NWORD + w * 2 + 1] = w1;
    }

    // ---- gather ----
    float4 acc = make_float4(0.f, 0.f, 0.f, 0.f);
    int j = sub;
    for (; j + 2 < cnt; j += 4) {          // 2 independent edges in flight
        int2 cva = ep[j];
        int2 cvb = ep[j + 2];
        float4 xa = ((const float4*)(g_ego + (size_t)cva.x * DIM))[dl];
        float4 xb = ((const float4*)(g_ego + (size_t)cvb.x * DIM))[dl];
        float va = __int_as_float(cva.y), vb = __int_as_float(cvb.y);
        acc.x += va * xa.x + vb * xb.x;
        acc.y += va * xa.y + vb * xb.y;
        acc.z += va * xa.z + vb * xb.z;
        acc.w += va * xa.w + vb * xb.w;
    }
    if (j < cnt) {
        int2 cv = ep[j];
        float v = __int_as_float(cv.y);
        float4 x = ((const float4*)(g_ego + (size_t)cv.x * DIM))[dl];
        acc.x += v * x.x; acc.y += v * x.y; acc.z += v * x.z; acc.w += v * x.w;
    }
    acc.x += __shfl_xor_sync(0xFFFFFFFFu, acc.x, 16);
    acc.y += __shfl_xor_sync(0xFFFFFFFFu, acc.y, 16);
    acc.z += __shfl_xor_sync(0xFFFFFFFFu, acc.z, 16);
    acc.w += __shfl_xor_sync(0xFFFFFFFFu, acc.w, 16);
    if (sub == 0)
        ((float4*)(g_side + (size_t)w * DIM))[dl] = acc;
}

// tf32 tensor-core combine:
// C[128x64] = A[128x128] @ B[128x64] + bias, leaky_relu, -> g_ego.
// A = [side | side*ego] (per 128-row tile), B = [W_gc ; W_bi] stacked on K.
// 256 threads = 8 warps; warp w computes rows [w*16, w*16+16) x all 64 cols
// via mma.sync m16n8k8 tf32 (fp32 accum).
__global__ void combine_kernel(const float* __restrict__ Wg, const float* __restrict__ bg,
                               const float* __restrict__ Wb, const float* __restrict__ bb) {
    extern __shared__ uint32_t smem_u[];
    uint32_t* sA    = smem_u;                              // 128 x A_STRIDE
    uint32_t* sB    = sA + RPB * A_STRIDE;                 // 128 x B_STRIDE
    float*    sbias = (float*)(sB + 128 * B_STRIDE);       // 64

    int tid  = threadIdx.x;
    int row0 = blockIdx.x * RPB;

    // ---- build B (tf32) + bias ----
    for (int i = tid; i < 8192; i += 256) {
        int k = i >> 6, n = i & 63;
        float v = (k < 64) ? Wg[k * 64 + n] : Wb[(k - 64) * 64 + n];
        sB[k * B_STRIDE + n] = f2tf32(v);
    }
    if (tid < 64) sbias[tid] = bg[tid] + bb[tid];

    // ---- build A (tf32): cols 0..63 = side, 64..127 = side*ego ----
    for (int i = tid; i < RPB * 16; i += 256) {
        int r = i >> 4, q = i & 15;
        int gr = row0 + r;
        float4 s = make_float4(0.f, 0.f, 0.f, 0.f), e = s;
        if (gr < NTOT) {
            s = ((const float4*)(g_side + (size_t)gr * DIM))[q];
            e = ((const float4*)(g_ego  + (size_t)gr * DIM))[q];
        }
        uint4 us = make_uint4(f2tf32(s.x), f2tf32(s.y), f2tf32(s.z), f2tf32(s.w));
        uint4 ue = make_uint4(f2tf32(s.x * e.x), f2tf32(s.y * e.y),
                              f2tf32(s.z * e.z), f2tf32(s.w * e.w));
        *(uint4*)&sA[r * A_STRIDE + q * 4]      = us;
        *(uint4*)&sA[r * A_STRIDE + 64 + q * 4] = ue;
    }
    __syncthreads();

    int w    = tid >> 5;
    int lane = tid & 31;
    int g    = lane >> 2;       // group id 0..7
    int tg   = lane & 3;        // thread-in-group 0..3

    // accumulators: 8 n-tiles x {c0,c1,c2,c3}
    float c[8][4];
#pragma unroll
    for (int nt = 0; nt < 8; nt++) {
        int col0 = nt * 8 + tg * 2;
        float b0 = sbias[col0], b1 = sbias[col0 + 1];
        c[nt][0] = b0; c[nt][1] = b1;   // row g
        c[nt][2] = b0; c[nt][3] = b1;   // row g+8
    }

    const uint32_t* Abase = sA + (w * 16 + g) * A_STRIDE + tg;
#pragma unroll
    for (int k16 = 0; k16 < 16; k16++) {
        int kb = k16 * 8;
        uint32_t a0 = Abase[kb];
        uint32_t a1 = Abase[8 * A_STRIDE + kb];
        uint32_t a2 = Abase[kb + 4];
        uint32_t a3 = Abase[8 * A_STRIDE + kb + 4];
        const uint32_t* Bb = sB + (kb + tg) * B_STRIDE + g;
#pragma unroll
        for (int nt = 0; nt < 8; nt++) {
            uint32_t b0 = Bb[nt * 8];
            uint32_t b1 = Bb[4 * B_STRIDE + nt * 8];
            mma_tf32(c[nt], a0, a1, a2, a3, b0, b1);
        }
    }

    // ---- epilogue: leaky-relu, store rows g and g+8 ----
    int r0 = row0 + w * 16 + g;
    int r1 = r0 + 8;
#pragma unroll
    for (int nt = 0; nt < 8; nt++) {
        int col0 = nt * 8 + tg * 2;
#pragma unroll
        for (int q = 0; q < 4; q++)
            c[nt][q] = (c[nt][q] >= 0.f) ? c[nt][q] : 0.2f * c[nt][q];
        if (r0 < NTOT)
            *(float2*)(g_ego + (size_t)r0 * DIM + col0) = make_float2(c[nt][0], c[nt][1]);
        if (r1 < NTOT)
            *(float2*)(g_ego + (size_t)r1 * DIM + col0) = make_float2(c[nt][2], c[nt][3]);
    }
}

// Msg dropout (precomputed bitmask) + row L2 normalize. Warp per row.
// Dropped un-normalized ego -> g_ego (skipped on last layer), normalized -> g_all.
__global__ void msgnorm_kernel(int layer, int write_ego) {
    int w    = (blockIdx.x * blockDim.x + threadIdx.x) >> 5;
    int lane = threadIdx.x & 31;
    if (w >= NTOT) return;
    size_t base = (size_t)w * DIM;
    float2 v = ((const float2*)(g_ego + base))[lane];
    uint32_t mw = g_mask[(size_t)layer * NWORD + w * 2 + (lane >> 4)];
    int sh = (lane * 2) & 31;
    v.x = ((mw >> sh) & 1u)       ? v.x * (1.0f / 0.9f) : 0.f;
    v.y = ((mw >> (sh + 1)) & 1u) ? v.y * (1.0f / 0.9f) : 0.f;
    if (write_ego)
        ((float2*)(g_ego + base))[lane] = v;

    float ss = v.x * v.x + v.y * v.y;
#pragma unroll
    for (int o = 16; o; o >>= 1) ss += __shfl_xor_sync(0xFFFFFFFFu, ss, o);
    float inv = 1.0f / fmaxf(sqrtf(ss), 1e-12f);
    float* dst = g_all + (size_t)w * CDIM2 + (size_t)layer * DIM;
    ((float2*)dst)[lane] = make_float2(v.x * inv, v.y * inv);
}

// warp per sample: BPR + reg partial sums. Concat = [raw emb | g_all(192)].
__global__ void loss_kernel(const float* __restrict__ ue0, const float* __restrict__ ie0,
                            const int* __restrict__ uid, const int* __restrict__ pid,
                            const int* __restrict__ nid) {
    int w    = (blockIdx.x * blockDim.x + threadIdx.x) >> 5;
    int lane = threadIdx.x & 31;
    if (w >= BSZ) return;
    int u = uid[w], p = pid[w], n = nid[w];
    const float* au = (lane < 8) ? ue0 + (size_t)u * DIM + lane * 8
                                 : g_all + (size_t)u * CDIM2 + lane * 8 - 64;
    const float* bp = (lane < 8) ? ie0 + (size_t)p * DIM + lane * 8
                                 : g_all + (size_t)(UNUM + p) * CDIM2 + lane * 8 - 64;
    const float* bn = (lane < 8) ? ie0 + (size_t)n * DIM + lane * 8
                                 : g_all + (size_t)(UNUM + n) * CDIM2 + lane * 8 - 64;
    float pos = 0.f, neg = 0.f;
#pragma unroll
    for (int t = 0; t < 2; t++) {
        float4 a = ((const float4*)au)[t];
        float4 b = ((const float4*)bp)[t];
        float4 c = ((const float4*)bn)[t];
        pos += a.x * b.x + a.y * b.y + a.z * b.z + a.w * b.w;
        neg += a.x * c.x + a.y * c.y + a.z * c.z + a.w * c.w;
    }
    float2 a0 = ((const float2*)(ue0 + (size_t)u * DIM))[lane];
    float2 b0 = ((const float2*)(ie0 + (size_t)p * DIM))[lane];
    float2 c0 = ((const float2*)(ie0 + (size_t)n * DIM))[lane];
    float rg = a0.x * a0.x + a0.y * a0.y + b0.x * b0.x + b0.y * b0.y + c0.x * c0.x + c0.y * c0.y;
#pragma unroll
    for (int o = 16; o; o >>= 1) {
        pos += __shfl_xor_sync(0xFFFFFFFFu, pos, o);
        neg += __shfl_xor_sync(0xFFFFFFFFu, neg, o);
        rg  += __shfl_xor_sync(0xFFFFFFFFu, rg,  o);
    }
    if (lane == 0) {
        float x = pos - neg;
        float ls = fminf(x, 0.f) - log1pf(expf(-fabsf(x)));  // stable log_sigmoid
        atomicAdd(&g_acc[0], ls);
        atomicAdd(&g_acc[1], rg);
    }
}

__global__ void fin_kernel(float* out, int osz) {
    float bpr = -g_acc[0] / (float)BSZ;
    float reg = 1e-4f * 0.5f * g_acc[1] / (float)BSZ;
    if (osz >= 3) { out[0] = bpr + reg; out[1] = bpr; out[2] = reg; }
    else          { out[0] = bpr + reg; }
}

// ---------------- launch ----------------
extern "C" void kernel_launch(void* const* d_in, const int* in_sizes, int n_in,
                              void* d_out, int out_size) {
    const float* user_emb = (const float*)d_in[0];
    const float* item_emb = (const float*)d_in[1];
    const float* W_gc     = (const float*)d_in[2];
    const float* b_gc     = (const float*)d_in[3];
    const float* W_bi     = (const float*)d_in[4];
    const float* b_bi     = (const float*)d_in[5];
    const float* val      = (const float*)d_in[6];
    const int*   row      = (const int*)d_in[7];
    const int*   col      = (const int*)d_in[8];
    const int*   uid      = (const int*)d_in[9];
    const int*   pid      = (const int*)d_in[10];
    const int*   nid      = (const int*)d_in[11];

    // derived threefry keys: base key = (0, 42); fold_in(d) = threefry(key, (0, d))
    uint32_t ke0, ke1;
    threefry2x32(0u, 42u, 0u, 0u, ke0, ke1);
    uint32_t mk0[NLAY], mk1[NLAY];
    for (int k = 0; k < NLAY; k++)
        threefry2x32(0u, 42u, 0u, (uint32_t)(k + 1), mk0[k], mk1[k]);

    const size_t SMEM = (RPB * A_STRIDE + 128 * B_STRIDE) * 4 + 64 * 4;  // ~104.7 KB
    static bool attr_set = false;
    if (!attr_set) {
        cudaFuncSetAttribute(combine_kernel, cudaFuncAttributeMaxDynamicSharedMemorySize, (int)SMEM);
        attr_set = true;
    }

    void* cnt_ptr = nullptr;
    cudaGetSymbolAddress(&cnt_ptr, g_cnt);

    cudaMemsetAsync(cnt_ptr, 0, NTOT * sizeof(int));
    init_kernel<<<(NTOT * DIM + 255) / 256, 256>>>(user_emb, item_emb);
    scatter_kernel<<<(NNZE + 255) / 256, 256>>>(val, row, col, ke0, ke1);

    for (int k = 0; k < NLAY; k++) {
        spmm_kernel<<<(NTOT * 32 + 255) / 256, 256>>>(mk0[k], mk1[k], k);
        combine_kernel<<<(NTOT + RPB - 1) / RPB, 256, SMEM>>>(
            W_gc + k * 4096, b_gc + k * 64, W_bi + k * 4096, b_bi + k * 64);
        msgnorm_kernel<<<(NTOT * 32 + 255) / 256, 256>>>(k, (k != NLAY - 1) ? 1 : 0);
    }

    loss_kernel<<<(BSZ * 32 + 255) / 256, 256>>>(user_emb, item_emb, uid, pid, nid);
    fin_kernel<<<1, 1>>>((float*)d_out, out_size);
}

// round 11
// speedup vs baseline: 1.7081x; 1.1121x over previous
#include <cuda_runtime.h>
#include <cstdint>

#define UNUM 100000
#define INUM 200000
#define NTOT 300000
#define NNZE 4000000
#define BSZ  4096
#define DIM  64
#define NLAY 3
#define CDIM2 192             // concat store: layers 1..3 only (layer0 read from inputs)
#define EMAX 96               // padded ELL row capacity (mean deg ~12)
#define RPB  128              // rows per combine block
#define NELEM (NTOT * DIM)    // 19,200,000 elems per layer
#define NWORD (NELEM / 32)    // 600,000 mask words per layer

#define A_STRIDE 132          // words; %32==4 -> conflict-free A frag loads
#define B_STRIDE 72           // words; %32==8 -> conflict-free B frag loads

// ---------------- scratch (static device globals; no allocs allowed) ----------------
__device__ __align__(256) float    g_ego [(size_t)NTOT * DIM];       // 76.8 MB
__device__ __align__(256) float    g_side[(size_t)NTOT * DIM];       // 76.8 MB
__device__ __align__(256) float    g_all [(size_t)NTOT * CDIM2];     // 230 MB
__device__ __align__(256) int2     g_ell [(size_t)NTOT * EMAX];      // 230 MB {col, val bits}
__device__ __align__(256) int      g_cnt [NTOT];
__device__ __align__(256) uint32_t g_mask[(size_t)NLAY * NWORD];     // 7.2 MB bit-packed
__device__ float g_acc[2];                                           // bpr_sum, reg_sum

// ---------------- threefry2x32 (exact JAX semantics) ----------------
__host__ __device__ __forceinline__ uint32_t rotl32(uint32_t x, int r) {
    return (x << r) | (x >> (32 - r));
}

__host__ __device__ inline void threefry2x32(uint32_t k0, uint32_t k1,
                                             uint32_t x0, uint32_t x1,
                                             uint32_t &o0, uint32_t &o1) {
    uint32_t k2 = k0 ^ k1 ^ 0x1BD11BDAu;
    x0 += k0; x1 += k1;
#define TF_R(r) { x0 += x1; x1 = rotl32(x1, r); x1 ^= x0; }
    TF_R(13) TF_R(15) TF_R(26) TF_R(6)   x0 += k1; x1 += k2 + 1u;
    TF_R(17) TF_R(29) TF_R(16) TF_R(24)  x0 += k2; x1 += k0 + 2u;
    TF_R(13) TF_R(15) TF_R(26) TF_R(6)   x0 += k0; x1 += k1 + 3u;
    TF_R(17) TF_R(29) TF_R(16) TF_R(24)  x0 += k1; x1 += k2 + 4u;
    TF_R(13) TF_R(15) TF_R(26) TF_R(6)   x0 += k2; x1 += k0 + 5u;
#undef TF_R
    o0 = x0; o1 = x1;
}

// Partitionable (counter-mode) bits: threefry(key, (0, i)), 32-bit finisher o0^o1
__device__ __forceinline__ uint32_t rbits_partitionable(uint32_t k0, uint32_t k1, uint32_t i) {
    uint32_t o0, o1;
    threefry2x32(k0, k1, 0u, i, o0, o1);
    return o0 ^ o1;
}

__device__ __forceinline__ float u01(uint32_t bits) {
    return __uint_as_float((bits >> 9) | 0x3F800000u) - 1.0f;
}

__device__ __forceinline__ uint32_t f2tf32(float x) {
    uint32_t r;
    asm("cvt.rna.tf32.f32 %0, %1;" : "=r"(r) : "f"(x));
    return r;
}

__device__ __forceinline__ void mma_tf32(float c[4], uint32_t a0, uint32_t a1,
                                         uint32_t a2, uint32_t a3,
                                         uint32_t b0, uint32_t b1) {
    asm volatile(
        "mma.sync.aligned.m16n8k8.row.col.f32.tf32.tf32.f32 "
        "{%0,%1,%2,%3}, {%4,%5,%6,%7}, {%8,%9}, {%0,%1,%2,%3};\n"
        : "+f"(c[0]), "+f"(c[1]), "+f"(c[2]), "+f"(c[3])
        : "r"(a0), "r"(a1), "r"(a2), "r"(a3), "r"(b0), "r"(b1));
}

// ---------------- kernels ----------------
// One pass: edge dropout + ELL scatter (dropped edges never stored). Zeroes acc.
__global__ void scatter_kernel(const float* __restrict__ val, const int* __restrict__ row,
                               const int* __restrict__ col, uint32_t k0, uint32_t k1) {
    int e = blockIdx.x * blockDim.x + threadIdx.x;
    if (e == 0) { g_acc[0] = 0.f; g_acc[1] = 0.f; }
    if (e >= NNZE) return;
    float u = u01(rbits_partitionable(k0, k1, (uint32_t)e));
    if (u >= 0.9f) return;                 // dropped: contributes +0 exactly
    float v = val[e] * (1.0f / 0.9f);
    int r = row[e];
    int pos = atomicAdd(&g_cnt[r], 1);
    if (pos < EMAX)
        g_ell[(size_t)r * EMAX + pos] = make_int2(col[e], __float_as_int(v));
}

// Atomic-free SpMM: warp per row; 2 edge-slots x 16 dim-lanes, 2-way unroll (MLP=2).
// Layer-0 reads raw embeddings via predicated pointer select (eu/ei).
// ALSO generates this layer's dropout mask words (hidden in gather-stall slots).
__global__ void spmm_kernel(const float* __restrict__ eu, const float* __restrict__ ei,
                            uint32_t mk0, uint32_t mk1, int layer) {
    int w    = (blockIdx.x * blockDim.x + threadIdx.x) >> 5;
    if (w >= NTOT) return;
    int lane = threadIdx.x & 31;
    int sub  = lane >> 4;       // which edge slot
    int dl   = lane & 15;       // dim quarter (float4)
    int cnt  = g_cnt[w];
    if (cnt > EMAX) cnt = EMAX;
    const int2* ep = g_ell + (size_t)w * EMAX;

    // ---- mask generation for row w (words 2w, 2w+1 of this layer) ----
    uint32_t eb = (uint32_t)w * 64u + (uint32_t)lane;
    bool keep0 = u01(rbits_partitionable(mk0, mk1, eb))       < 0.9f;
    bool keep1 = u01(rbits_partitionable(mk0, mk1, eb + 32u)) < 0.9f;
    uint32_t w0 = __ballot_sync(0xFFFFFFFFu, keep0);
    uint32_t w1 = __ballot_sync(0xFFFFFFFFu, keep1);
    if (lane == 0) {
        g_mask[(size_t)layer * NWORD + w * 2]     = w0;
        g_mask[(size_t)layer * NWORD + w * 2 + 1] = w1;
    }

    // ---- gather ----
    float4 acc = make_float4(0.f, 0.f, 0.f, 0.f);
    int j = sub;
    for (; j + 2 < cnt; j += 4) {          // 2 independent edges in flight
        int2 cva = ep[j];
        int2 cvb = ep[j + 2];
        const float* ra = (cva.x < UNUM) ? eu + (size_t)cva.x * DIM
                                         : ei + (size_t)(cva.x - UNUM) * DIM;
        const float* rb = (cvb.x < UNUM) ? eu + (size_t)cvb.x * DIM
                                         : ei + (size_t)(cvb.x - UNUM) * DIM;
        float4 xa = ((const float4*)ra)[dl];
        float4 xb = ((const float4*)rb)[dl];
        float va = __int_as_float(cva.y), vb = __int_as_float(cvb.y);
        acc.x += va * xa.x + vb * xb.x;
        acc.y += va * xa.y + vb * xb.y;
        acc.z += va * xa.z + vb * xb.z;
        acc.w += va * xa.w + vb * xb.w;
    }
    if (j < cnt) {
        int2 cv = ep[j];
        const float* rr = (cv.x < UNUM) ? eu + (size_t)cv.x * DIM
                                        : ei + (size_t)(cv.x - UNUM) * DIM;
        float v = __int_as_float(cv.y);
        float4 x = ((const float4*)rr)[dl];
        acc.x += v * x.x; acc.y += v * x.y; acc.z += v * x.z; acc.w += v * x.w;
    }
    acc.x += __shfl_xor_sync(0xFFFFFFFFu, acc.x, 16);
    acc.y += __shfl_xor_sync(0xFFFFFFFFu, acc.y, 16);
    acc.z += __shfl_xor_sync(0xFFFFFFFFu, acc.z, 16);
    acc.w += __shfl_xor_sync(0xFFFFFFFFu, acc.w, 16);
    if (sub == 0)
        ((float4*)(g_side + (size_t)w * DIM))[dl] = acc;
}

// tf32 tensor-core combine + FUSED dropout/normalize epilogue:
// C[128x64] = A[128x128] @ B[128x64] + bias -> leaky_relu -> mask dropout
//  -> dropped ego (g_ego, unless last layer) + L2-normalized concat (g_all).
__global__ void combine_kernel(const float* __restrict__ Wg, const float* __restrict__ bg,
                               const float* __restrict__ Wb, const float* __restrict__ bb,
                               const float* __restrict__ eu, const float* __restrict__ ei,
                               int layer, int write_ego) {
    extern __shared__ uint32_t smem_u[];
    uint32_t* sA    = smem_u;                              // 128 x A_STRIDE
    uint32_t* sB    = sA + RPB * A_STRIDE;                 // 128 x B_STRIDE
    float*    sbias = (float*)(sB + 128 * B_STRIDE);       // 64

    int tid  = threadIdx.x;
    int row0 = blockIdx.x * RPB;

    // ---- build B (tf32) + bias ----
    for (int i = tid; i < 8192; i += 256) {
        int k = i >> 6, n = i & 63;
        float v = (k < 64) ? Wg[k * 64 + n] : Wb[(k - 64) * 64 + n];
        sB[k * B_STRIDE + n] = f2tf32(v);
    }
    if (tid < 64) sbias[tid] = bg[tid] + bb[tid];

    // ---- build A (tf32): cols 0..63 = side, 64..127 = side*ego ----
    for (int i = tid; i < RPB * 16; i += 256) {
        int r = i >> 4, q = i & 15;
        int gr = row0 + r;
        float4 s = make_float4(0.f, 0.f, 0.f, 0.f), e = s;
        if (gr < NTOT) {
            s = ((const float4*)(g_side + (size_t)gr * DIM))[q];
            const float* erow = (gr < UNUM) ? eu + (size_t)gr * DIM
                                            : ei + (size_t)(gr - UNUM) * DIM;
            e = ((const float4*)erow)[q];
        }
        uint4 us = make_uint4(f2tf32(s.x), f2tf32(s.y), f2tf32(s.z), f2tf32(s.w));
        uint4 ue = make_uint4(f2tf32(s.x * e.x), f2tf32(s.y * e.y),
                              f2tf32(s.z * e.z), f2tf32(s.w * e.w));
        *(uint4*)&sA[r * A_STRIDE + q * 4]      = us;
        *(uint4*)&sA[r * A_STRIDE + 64 + q * 4] = ue;
    }
    __syncthreads();

    int w    = tid >> 5;
    int lane = tid & 31;
    int g    = lane >> 2;       // group id 0..7
    int tg   = lane & 3;        // thread-in-group 0..3

    // accumulators: 8 n-tiles x {c0,c1,c2,c3}
    float c[8][4];
#pragma unroll
    for (int nt = 0; nt < 8; nt++) {
        int col0 = nt * 8 + tg * 2;
        float b0 = sbias[col0], b1 = sbias[col0 + 1];
        c[nt][0] = b0; c[nt][1] = b1;   // row g
        c[nt][2] = b0; c[nt][3] = b1;   // row g+8
    }

    const uint32_t* Abase = sA + (w * 16 + g) * A_STRIDE + tg;
#pragma unroll
    for (int k16 = 0; k16 < 16; k16++) {
        int kb = k16 * 8;
        uint32_t a0 = Abase[kb];
        uint32_t a1 = Abase[8 * A_STRIDE + kb];
        uint32_t a2 = Abase[kb + 4];
        uint32_t a3 = Abase[8 * A_STRIDE + kb + 4];
        const uint32_t* Bb = sB + (kb + tg) * B_STRIDE + g;
#pragma unroll
        for (int nt = 0; nt < 8; nt++) {
            uint32_t b0 = Bb[nt * 8];
            uint32_t b1 = Bb[4 * B_STRIDE + nt * 8];
            mma_tf32(c[nt], a0, a1, a2, a3, b0, b1);
        }
    }

    // ---- fused epilogue: leaky_relu -> dropout (bitmask) -> L2 norm ----
    int r0 = row0 + w * 16 + g;
    int r1 = r0 + 8;
    const uint32_t* mb = g_mask + (size_t)layer * NWORD;
    uint2 m0 = (r0 < NTOT) ? *(const uint2*)&mb[2 * r0] : make_uint2(0u, 0u);
    uint2 m1 = (r1 < NTOT) ? *(const uint2*)&mb[2 * r1] : make_uint2(0u, 0u);

    float ss0 = 0.f, ss1 = 0.f;
#pragma unroll
    for (int nt = 0; nt < 8; nt++) {
        int col0 = nt * 8 + tg * 2;
#pragma unroll
        for (int q = 0; q < 2; q++) {
            int col = col0 + q;
            uint32_t bit0 = ((col < 32 ? m0.x : m0.y) >> (col & 31)) & 1u;
            uint32_t bit1 = ((col < 32 ? m1.x : m1.y) >> (col & 31)) & 1u;
            float a = c[nt][q];
            a = (a >= 0.f) ? a : 0.2f * a;
            a = bit0 ? a * (1.0f / 0.9f) : 0.f;
            c[nt][q] = a;
            ss0 += a * a;
            float b = c[nt][2 + q];
            b = (b >= 0.f) ? b : 0.2f * b;
            b = bit1 ? b * (1.0f / 0.9f) : 0.f;
            c[nt][2 + q] = b;
            ss1 += b * b;
        }
    }
    // reduce over the 4 threads (tg) holding this row's 64 cols
    ss0 += __shfl_xor_sync(0xFFFFFFFFu, ss0, 1);
    ss0 += __shfl_xor_sync(0xFFFFFFFFu, ss0, 2);
    ss1 += __shfl_xor_sync(0xFFFFFFFFu, ss1, 1);
    ss1 += __shfl_xor_sync(0xFFFFFFFFu, ss1, 2);
    float inv0 = 1.0f / fmaxf(sqrtf(ss0), 1e-12f);
    float inv1 = 1.0f / fmaxf(sqrtf(ss1), 1e-12f);

    float* all0 = g_all + (size_t)r0 * CDIM2 + (size_t)layer * DIM;
    float* all1 = g_all + (size_t)r1 * CDIM2 + (size_t)layer * DIM;
#pragma unroll
    for (int nt = 0; nt < 8; nt++) {
        int col0 = nt * 8 + tg * 2;
        if (r0 < NTOT) {
            *(float2*)(all0 + col0) = make_float2(c[nt][0] * inv0, c[nt][1] * inv0);
            if (write_ego)
                *(float2*)(g_ego + (size_t)r0 * DIM + col0) = make_float2(c[nt][0], c[nt][1]);
        }
        if (r1 < NTOT) {
            *(float2*)(all1 + col0) = make_float2(c[nt][2] * inv1, c[nt][3] * inv1);
            if (write_ego)
                *(float2*)(g_ego + (size_t)r1 * DIM + col0) = make_float2(c[nt][2], c[nt][3]);
        }
    }
}

// warp per sample: BPR + reg partial sums. Concat = [raw emb | g_all(192)].
__global__ void loss_kernel(const float* __restrict__ ue0, const float* __restrict__ ie0,
                            const int* __restrict__ uid, const int* __restrict__ pid,
                            const int* __restrict__ nid) {
    int w    = (blockIdx.x * blockDim.x + threadIdx.x) >> 5;
    int lane = threadIdx.x & 31;
    if (w >= BSZ) return;
    int u = uid[w], p = pid[w], n = nid[w];
    const float* au = (lane < 8) ? ue0 + (size_t)u * DIM + lane * 8
                                 : g_all + (size_t)u * CDIM2 + lane * 8 - 64;
    const float* bp = (lane < 8) ? ie0 + (size_t)p * DIM + lane * 8
                                 : g_all + (size_t)(UNUM + p) * CDIM2 + lane * 8 - 64;
    const float* bn = (lane < 8) ? ie0 + (size_t)n * DIM + lane * 8
                                 : g_all + (size_t)(UNUM + n) * CDIM2 + lane * 8 - 64;
    float pos = 0.f, neg = 0.f;
#pragma unroll
    for (int t = 0; t < 2; t++) {
        float4 a = ((const float4*)au)[t];
        float4 b = ((const float4*)bp)[t];
        float4 c = ((const float4*)bn)[t];
        pos += a.x * b.x + a.y * b.y + a.z * b.z + a.w * b.w;
        neg += a.x * c.x + a.y * c.y + a.z * c.z + a.w * c.w;
    }
    float2 a0 = ((const float2*)(ue0 + (size_t)u * DIM))[lane];
    float2 b0 = ((const float2*)(ie0 + (size_t)p * DIM))[lane];
    float2 c0 = ((const float2*)(ie0 + (size_t)n * DIM))[lane];
    float rg = a0.x * a0.x + a0.y * a0.y + b0.x * b0.x + b0.y * b0.y + c0.x * c0.x + c0.y * c0.y;
#pragma unroll
    for (int o = 16; o; o >>= 1) {
        pos += __shfl_xor_sync(0xFFFFFFFFu, pos, o);
        neg += __shfl_xor_sync(0xFFFFFFFFu, neg, o);
        rg  += __shfl_xor_sync(0xFFFFFFFFu, rg,  o);
    }
    if (lane == 0) {
        float x = pos - neg;
        float ls = fminf(x, 0.f) - log1pf(expf(-fabsf(x)));  // stable log_sigmoid
        atomicAdd(&g_acc[0], ls);
        atomicAdd(&g_acc[1], rg);
    }
}

__global__ void fin_kernel(float* out, int osz) {
    float bpr = -g_acc[0] / (float)BSZ;
    float reg = 1e-4f * 0.5f * g_acc[1] / (float)BSZ;
    if (osz >= 3) { out[0] = bpr + reg; out[1] = bpr; out[2] = reg; }
    else          { out[0] = bpr + reg; }
}

// ---------------- launch ----------------
extern "C" void kernel_launch(void* const* d_in, const int* in_sizes, int n_in,
                              void* d_out, int out_size) {
    const float* user_emb = (const float*)d_in[0];
    const float* item_emb = (const float*)d_in[1];
    const float* W_gc     = (const float*)d_in[2];
    const float* b_gc     = (const float*)d_in[3];
    const float* W_bi     = (const float*)d_in[4];
    const float* b_bi     = (const float*)d_in[5];
    const float* val      = (const float*)d_in[6];
    const int*   row      = (const int*)d_in[7];
    const int*   col      = (const int*)d_in[8];
    const int*   uid      = (const int*)d_in[9];
    const int*   pid      = (const int*)d_in[10];
    const int*   nid      = (const int*)d_in[11];

    // derived threefry keys: base key = (0, 42); fold_in(d) = threefry(key, (0, d))
    uint32_t ke0, ke1;
    threefry2x32(0u, 42u, 0u, 0u, ke0, ke1);
    uint32_t mk0[NLAY], mk1[NLAY];
    for (int k = 0; k < NLAY; k++)
        threefry2x32(0u, 42u, 0u, (uint32_t)(k + 1), mk0[k], mk1[k]);

    const size_t SMEM = (RPB * A_STRIDE + 128 * B_STRIDE) * 4 + 64 * 4;  // ~104.7 KB
    static bool attr_set = false;
    if (!attr_set) {
        cudaFuncSetAttribute(combine_kernel, cudaFuncAttributeMaxDynamicSharedMemorySize, (int)SMEM);
        attr_set = true;
    }

    void* cnt_ptr = nullptr;
    cudaGetSymbolAddress(&cnt_ptr, g_cnt);
    float* g_ego_ptr = nullptr;
    { void* tmp = nullptr; cudaGetSymbolAddress(&tmp, g_ego); g_ego_ptr = (float*)tmp; }

    cudaMemsetAsync(cnt_ptr, 0, NTOT * sizeof(int));
    scatter_kernel<<<(NNZE + 255) / 256, 256>>>(val, row, col, ke0, ke1);

    for (int k = 0; k < NLAY; k++) {
        const float* eu = (k == 0) ? user_emb : g_ego_ptr;
        const float* ei = (k == 0) ? item_emb : g_ego_ptr + (size_t)UNUM * DIM;
        spmm_kernel<<<(NTOT * 32 + 255) / 256, 256>>>(eu, ei, mk0[k], mk1[k], k);
        combine_kernel<<<(NTOT + RPB - 1) / RPB, 256, SMEM>>>(
            W_gc + k * 4096, b_gc + k * 64, W_bi + k * 4096, b_bi + k * 64,
            eu, ei, k, (k != NLAY - 1) ? 1 : 0);
    }

    loss_kernel<<<(BSZ * 32 + 255) / 256, 256>>>(user_emb, item_emb, uid, pid, nid);
    fin_kernel<<<1, 1>>>((float*)d_out, out_size);
}

// round 14
// speedup vs baseline: 1.9611x; 1.1481x over previous
#include <cuda_runtime.h>
#include <cstdint>

#define UNUM 100000
#define INUM 200000
#define NTOT 300000
#define NNZE 4000000
#define BSZ  4096
#define DIM  64
#define NLAY 3
#define CDIM2 192             // concat store: layers 1..3 only (layer0 read from inputs)
#define EMAX 96               // padded ELL row capacity (mean deg ~12)
#define RPB  128              // rows per combine block
#define NELEM (NTOT * DIM)    // 19,200,000 elems per layer
#define NWORD (NELEM / 32)    // 600,000 mask words per layer

#define A_STRIDE 132          // words; %32==4 -> conflict-free A frag loads
#define B_STRIDE 72           // words; %32==8 -> conflict-free B frag loads

// ---------------- scratch (static device globals; no allocs allowed) ----------------
__device__ __align__(256) float    g_ego [(size_t)NTOT * DIM];       // 76.8 MB
__device__ __align__(256) float    g_side[(size_t)NTOT * DIM];       // 76.8 MB
__device__ __align__(256) float    g_all [(size_t)NTOT * CDIM2];     // 230 MB
__device__ __align__(256) int2     g_ell [(size_t)NTOT * EMAX];      // 230 MB {col, val bits}
__device__ __align__(256) int      g_cnt [NTOT];
__device__ __align__(256) uint32_t g_mask[(size_t)NLAY * NWORD];     // 7.2 MB bit-packed
__device__ float g_acc[2];                                           // bpr_sum, reg_sum

// ---------------- threefry2x32 (exact JAX semantics) ----------------
__host__ __device__ __forceinline__ uint32_t rotl32(uint32_t x, int r) {
    return (x << r) | (x >> (32 - r));
}

__host__ __device__ inline void threefry2x32(uint32_t k0, uint32_t k1,
                                             uint32_t x0, uint32_t x1,
                                             uint32_t &o0, uint32_t &o1) {
    uint32_t k2 = k0 ^ k1 ^ 0x1BD11BDAu;
    x0 += k0; x1 += k1;
#define TF_R(r) { x0 += x1; x1 = rotl32(x1, r); x1 ^= x0; }
    TF_R(13) TF_R(15) TF_R(26) TF_R(6)   x0 += k1; x1 += k2 + 1u;
    TF_R(17) TF_R(29) TF_R(16) TF_R(24)  x0 += k2; x1 += k0 + 2u;
    TF_R(13) TF_R(15) TF_R(26) TF_R(6)   x0 += k0; x1 += k1 + 3u;
    TF_R(17) TF_R(29) TF_R(16) TF_R(24)  x0 += k1; x1 += k2 + 4u;
    TF_R(13) TF_R(15) TF_R(26) TF_R(6)   x0 += k2; x1 += k0 + 5u;
#undef TF_R
    o0 = x0; o1 = x1;
}

// Partitionable (counter-mode) bits: threefry(key, (0, i)), 32-bit finisher o0^o1
__device__ __forceinline__ uint32_t rbits_partitionable(uint32_t k0, uint32_t k1, uint32_t i) {
    uint32_t o0, o1;
    threefry2x32(k0, k1, 0u, i, o0, o1);
    return o0 ^ o1;
}

__device__ __forceinline__ float u01(uint32_t bits) {
    return __uint_as_float((bits >> 9) | 0x3F800000u) - 1.0f;
}

__device__ __forceinline__ uint32_t f2tf32(float x) {
    uint32_t r;
    asm("cvt.rna.tf32.f32 %0, %1;" : "=r"(r) : "f"(x));
    return r;
}

__device__ __forceinline__ void mma_tf32(float c[4], uint32_t a0, uint32_t a1,
                                         uint32_t a2, uint32_t a3,
                                         uint32_t b0, uint32_t b1) {
    asm volatile(
        "mma.sync.aligned.m16n8k8.row.col.f32.tf32.tf32.f32 "
        "{%0,%1,%2,%3}, {%4,%5,%6,%7}, {%8,%9}, {%0,%1,%2,%3};\n"
        : "+f"(c[0]), "+f"(c[1]), "+f"(c[2]), "+f"(c[3])
        : "r"(a0), "r"(a1), "r"(a2), "r"(a3), "r"(b0), "r"(b1));
}

// ---------------- kernels ----------------
// One pass: edge dropout + ELL scatter (dropped edges never stored). Zeroes acc.
__global__ void scatter_kernel(const float* __restrict__ val, const int* __restrict__ row,
                               const int* __restrict__ col, uint32_t k0, uint32_t k1) {
    int e = blockIdx.x * blockDim.x + threadIdx.x;
    if (e == 0) { g_acc[0] = 0.f; g_acc[1] = 0.f; }
    if (e >= NNZE) return;
    float u = u01(rbits_partitionable(k0, k1, (uint32_t)e));
    if (u >= 0.9f) return;                 // dropped: contributes +0 exactly
    float v = val[e] * (1.0f / 0.9f);
    int r = row[e];
    int pos = atomicAdd(&g_cnt[r], 1);
    if (pos < EMAX)
        g_ell[(size_t)r * EMAX + pos] = make_int2(col[e], __float_as_int(v));
}

// Atomic-free SpMM v2: HALF-WARP per row, 16 dim-lanes, 4-way predicated-clamp
// unroll (MLP=4 incl. tail, no cross-lane reduction). Warp wp covers rows
// 2wp, 2wp+1 -> mask words 4wp..4wp+3 via full-warp ballots.
__global__ void spmm_kernel(const float* __restrict__ eu, const float* __restrict__ ei,
                            uint32_t mk0, uint32_t mk1, int layer) {
    int wp   = (blockIdx.x * blockDim.x + threadIdx.x) >> 5;
    if (wp >= NTOT / 2) return;
    int lane = threadIdx.x & 31;
    int half = lane >> 4;
    int dl   = lane & 15;       // dim quarter (float4)
    int w    = wp * 2 + half;   // this half-warp's row

    // ---- mask generation: 128 elems [128wp, 128wp+128) -> words 4wp..4wp+3 ----
    uint32_t eb = (uint32_t)wp * 128u + (uint32_t)lane;
#pragma unroll
    for (int q = 0; q < 4; q++) {
        bool keep = u01(rbits_partitionable(mk0, mk1, eb + (uint32_t)(q * 32))) < 0.9f;
        uint32_t mwd = __ballot_sync(0xFFFFFFFFu, keep);
        if (lane == 0) g_mask[(size_t)layer * NWORD + wp * 4 + q] = mwd;
    }

    // ---- gather (4 edges in flight; tail clamps index, zeroes value) ----
    int cnt = g_cnt[w];
    if (cnt > EMAX) cnt = EMAX;
    const int2* ep = g_ell + (size_t)w * EMAX;
    float4 acc = make_float4(0.f, 0.f, 0.f, 0.f);
    for (int j = 0; j < cnt; j += 4) {
        int i1 = min(j + 1, cnt - 1);
        int i2 = min(j + 2, cnt - 1);
        int i3 = min(j + 3, cnt - 1);
        int2 c0 = ep[j], c1 = ep[i1], c2 = ep[i2], c3 = ep[i3];
        const float* r0 = (c0.x < UNUM) ? eu + (size_t)c0.x * DIM : ei + (size_t)(c0.x - UNUM) * DIM;
        const float* r1 = (c1.x < UNUM) ? eu + (size_t)c1.x * DIM : ei + (size_t)(c1.x - UNUM) * DIM;
        const float* r2 = (c2.x < UNUM) ? eu + (size_t)c2.x * DIM : ei + (size_t)(c2.x - UNUM) * DIM;
        const float* r3 = (c3.x < UNUM) ? eu + (size_t)c3.x * DIM : ei + (size_t)(c3.x - UNUM) * DIM;
        float4 x0 = ((const float4*)r0)[dl];
        float4 x1 = ((const float4*)r1)[dl];
        float4 x2 = ((const float4*)r2)[dl];
        float4 x3 = ((const float4*)r3)[dl];
        float v0 = __int_as_float(c0.y);
        float v1 = (j + 1 < cnt) ? __int_as_float(c1.y) : 0.f;
        float v2 = (j + 2 < cnt) ? __int_as_float(c2.y) : 0.f;
        float v3 = (j + 3 < cnt) ? __int_as_float(c3.y) : 0.f;
        acc.x += v0 * x0.x + v1 * x1.x + v2 * x2.x + v3 * x3.x;
        acc.y += v0 * x0.y + v1 * x1.y + v2 * x2.y + v3 * x3.y;
        acc.z += v0 * x0.z + v1 * x1.z + v2 * x2.z + v3 * x3.z;
        acc.w += v0 * x0.w + v1 * x1.w + v2 * x2.w + v3 * x3.w;
    }
    ((float4*)(g_side + (size_t)w * DIM))[dl] = acc;
}

// tf32 tensor-core combine + FUSED dropout/normalize epilogue:
// C[128x64] = A[128x128] @ B[128x64] + bias -> leaky_relu -> mask dropout
//  -> dropped ego (g_ego, unless last layer) + L2-normalized concat (g_all).
__global__ void combine_kernel(const float* __restrict__ Wg, const float* __restrict__ bg,
                               const float* __restrict__ Wb, const float* __restrict__ bb,
                               const float* __restrict__ eu, const float* __restrict__ ei,
                               int layer, int write_ego) {
    extern __shared__ uint32_t smem_u[];
    uint32_t* sA    = smem_u;                              // 128 x A_STRIDE
    uint32_t* sB    = sA + RPB * A_STRIDE;                 // 128 x B_STRIDE
    float*    sbias = (float*)(sB + 128 * B_STRIDE);       // 64

    int tid  = threadIdx.x;
    int row0 = blockIdx.x * RPB;

    // ---- build B (tf32) + bias ----
    for (int i = tid; i < 8192; i += 256) {
        int k = i >> 6, n = i & 63;
        float v = (k < 64) ? Wg[k * 64 + n] : Wb[(k - 64) * 64 + n];
        sB[k * B_STRIDE + n] = f2tf32(v);
    }
    if (tid < 64) sbias[tid] = bg[tid] + bb[tid];

    // ---- build A (tf32): cols 0..63 = side, 64..127 = side*ego ----
    for (int i = tid; i < RPB * 16; i += 256) {
        int r = i >> 4, q = i & 15;
        int gr = row0 + r;
        float4 s = make_float4(0.f, 0.f, 0.f, 0.f), e = s;
        if (gr < NTOT) {
            s = ((const float4*)(g_side + (size_t)gr * DIM))[q];
            const float* erow = (gr < UNUM) ? eu + (size_t)gr * DIM
                                            : ei + (size_t)(gr - UNUM) * DIM;
            e = ((const float4*)erow)[q];
        }
        uint4 us = make_uint4(f2tf32(s.x), f2tf32(s.y), f2tf32(s.z), f2tf32(s.w));
        uint4 ue = make_uint4(f2tf32(s.x * e.x), f2tf32(s.y * e.y),
                              f2tf32(s.z * e.z), f2tf32(s.w * e.w));
        *(uint4*)&sA[r * A_STRIDE + q * 4]      = us;
        *(uint4*)&sA[r * A_STRIDE + 64 + q * 4] = ue;
    }
    __syncthreads();

    int w    = tid >> 5;
    int lane = tid & 31;
    int g    = lane >> 2;       // group id 0..7
    int tg   = lane & 3;        // thread-in-group 0..3

    // accumulators: 8 n-tiles x {c0,c1,c2,c3}
    float c[8][4];
#pragma unroll
    for (int nt = 0; nt < 8; nt++) {
        int col0 = nt * 8 + tg * 2;
        float b0 = sbias[col0], b1 = sbias[col0 + 1];
        c[nt][0] = b0; c[nt][1] = b1;   // row g
        c[nt][2] = b0; c[nt][3] = b1;   // row g+8
    }

    const uint32_t* Abase = sA + (w * 16 + g) * A_STRIDE + tg;
#pragma unroll
    for (int k16 = 0; k16 < 16; k16++) {
        int kb = k16 * 8;
        uint32_t a0 = Abase[kb];
        uint32_t a1 = Abase[8 * A_STRIDE + kb];
        uint32_t a2 = Abase[kb + 4];
        uint32_t a3 = Abase[8 * A_STRIDE + kb + 4];
        const uint32_t* Bb = sB + (kb + tg) * B_STRIDE + g;
#pragma unroll
        for (int nt = 0; nt < 8; nt++) {
            uint32_t b0 = Bb[nt * 8];
            uint32_t b1 = Bb[4 * B_STRIDE + nt * 8];
            mma_tf32(c[nt], a0, a1, a2, a3, b0, b1);
        }
    }

    // ---- fused epilogue: leaky_relu -> dropout (bitmask) -> L2 norm ----
    int r0 = row0 + w * 16 + g;
    int r1 = r0 + 8;
    const uint32_t* mb = g_mask + (size_t)layer * NWORD;
    uint2 m0 = (r0 < NTOT) ? *(const uint2*)&mb[2 * r0] : make_uint2(0u, 0u);
    uint2 m1 = (r1 < NTOT) ? *(const uint2*)&mb[2 * r1] : make_uint2(0u, 0u);

    float ss0 = 0.f, ss1 = 0.f;
#pragma unroll
    for (int nt = 0; nt < 8; nt++) {
        int col0 = nt * 8 + tg * 2;
#pragma unroll
        for (int q = 0; q < 2; q++) {
            int col = col0 + q;
            uint32_t bit0 = ((col < 32 ? m0.x : m0.y) >> (col & 31)) & 1u;
            uint32_t bit1 = ((col < 32 ? m1.x : m1.y) >> (col & 31)) & 1u;
            float a = c[nt][q];
            a = (a >= 0.f) ? a : 0.2f * a;
            a = bit0 ? a * (1.0f / 0.9f) : 0.f;
            c[nt][q] = a;
            ss0 += a * a;
            float b = c[nt][2 + q];
            b = (b >= 0.f) ? b : 0.2f * b;
            b = bit1 ? b * (1.0f / 0.9f) : 0.f;
            c[nt][2 + q] = b;
            ss1 += b * b;
        }
    }
    // reduce over the 4 threads (tg) holding this row's 64 cols
    ss0 += __shfl_xor_sync(0xFFFFFFFFu, ss0, 1);
    ss0 += __shfl_xor_sync(0xFFFFFFFFu, ss0, 2);
    ss1 += __shfl_xor_sync(0xFFFFFFFFu, ss1, 1);
    ss1 += __shfl_xor_sync(0xFFFFFFFFu, ss1, 2);
    float inv0 = 1.0f / fmaxf(sqrtf(ss0), 1e-12f);
    float inv1 = 1.0f / fmaxf(sqrtf(ss1), 1e-12f);

    float* all0 = g_all + (size_t)r0 * CDIM2 + (size_t)layer * DIM;
    float* all1 = g_all + (size_t)r1 * CDIM2 + (size_t)layer * DIM;
#pragma unroll
    for (int nt = 0; nt < 8; nt++) {
        int col0 = nt * 8 + tg * 2;
        if (r0 < NTOT) {
            *(float2*)(all0 + col0) = make_float2(c[nt][0] * inv0, c[nt][1] * inv0);
            if (write_ego)
                *(float2*)(g_ego + (size_t)r0 * DIM + col0) = make_float2(c[nt][0], c[nt][1]);
        }
        if (r1 < NTOT) {
            *(float2*)(all1 + col0) = make_float2(c[nt][2] * inv1, c[nt][3] * inv1);
            if (write_ego)
                *(float2*)(g_ego + (size_t)r1 * DIM + col0) = make_float2(c[nt][2], c[nt][3]);
        }
    }
}

// warp per sample: BPR + reg partial sums. Concat = [raw emb | g_all(192)].
__global__ void loss_kernel(const float* __restrict__ ue0, const float* __restrict__ ie0,
                            const int* __restrict__ uid, const int* __restrict__ pid,
                            const int* __restrict__ nid) {
    int w    = (blockIdx.x * blockDim.x + threadIdx.x) >> 5;
    int lane = threadIdx.x & 31;
    if (w >= BSZ) return;
    int u = uid[w], p = pid[w], n = nid[w];
    const float* au = (lane < 8) ? ue0 + (size_t)u * DIM + lane * 8
                                 : g_all + (size_t)u * CDIM2 + lane * 8 - 64;
    const float* bp = (lane < 8) ? ie0 + (size_t)p * DIM + lane * 8
                                 : g_all + (size_t)(UNUM + p) * CDIM2 + lane * 8 - 64;
    const float* bn = (lane < 8) ? ie0 + (size_t)n * DIM + lane * 8
                                 : g_all + (size_t)(UNUM + n) * CDIM2 + lane * 8 - 64;
    float pos = 0.f, neg = 0.f;
#pragma unroll
    for (int t = 0; t < 2; t++) {
        float4 a = ((const float4*)au)[t];
        float4 b = ((const float4*)bp)[t];
        float4 c = ((const float4*)bn)[t];
        pos += a.x * b.x + a.y * b.y + a.z * b.z + a.w * b.w;
        neg += a.x * c.x + a.y * c.y + a.z * c.z + a.w * c.w;
    }
    float2 a0 = ((const float2*)(ue0 + (size_t)u * DIM))[lane];
    float2 b0 = ((const float2*)(ie0 + (size_t)p * DIM))[lane];
    float2 c0 = ((const float2*)(ie0 + (size_t)n * DIM))[lane];
    float rg = a0.x * a0.x + a0.y * a0.y + b0.x * b0.x + b0.y * b0.y + c0.x * c0.x + c0.y * c0.y;
#pragma unroll
    for (int o = 16; o; o >>= 1) {
        pos += __shfl_xor_sync(0xFFFFFFFFu, pos, o);
        neg += __shfl_xor_sync(0xFFFFFFFFu, neg, o);
        rg  += __shfl_xor_sync(0xFFFFFFFFu, rg,  o);
    }
    if (lane == 0) {
        float x = pos - neg;
        float ls = fminf(x, 0.f) - log1pf(expf(-fabsf(x)));  // stable log_sigmoid
        atomicAdd(&g_acc[0], ls);
        atomicAdd(&g_acc[1], rg);
    }
}

__global__ void fin_kernel(float* out, int osz) {
    float bpr = -g_acc[0] / (float)BSZ;
    float reg = 1e-4f * 0.5f * g_acc[1] / (float)BSZ;
    if (osz >= 3) { out[0] = bpr + reg; out[1] = bpr; out[2] = reg; }
    else          { out[0] = bpr + reg; }
}

// ---------------- launch ----------------
extern "C" void kernel_launch(void* const* d_in, const int* in_sizes, int n_in,
                              void* d_out, int out_size) {
    const float* user_emb = (const float*)d_in[0];
    const float* item_emb = (const float*)d_in[1];
    const float* W_gc     = (const float*)d_in[2];
    const float* b_gc     = (const float*)d_in[3];
    const float* W_bi     = (const float*)d_in[4];
    const float* b_bi     = (const float*)d_in[5];
    const float* val      = (const float*)d_in[6];
    const int*   row      = (const int*)d_in[7];
    const int*   col      = (const int*)d_in[8];
    const int*   uid      = (const int*)d_in[9];
    const int*   pid      = (const int*)d_in[10];
    const int*   nid      = (const int*)d_in[11];

    // derived threefry keys: base key = (0, 42); fold_in(d) = threefry(key, (0, d))
    uint32_t ke0, ke1;
    threefry2x32(0u, 42u, 0u, 0u, ke0, ke1);
    uint32_t mk0[NLAY], mk1[NLAY];
    for (int k = 0; k < NLAY; k++)
        threefry2x32(0u, 42u, 0u, (uint32_t)(k + 1), mk0[k], mk1[k]);

    const size_t SMEM = (RPB * A_STRIDE + 128 * B_STRIDE) * 4 + 64 * 4;  // ~104.7 KB
    static bool attr_set = false;
    if (!attr_set) {
        cudaFuncSetAttribute(combine_kernel, cudaFuncAttributeMaxDynamicSharedMemorySize, (int)SMEM);
        attr_set = true;
    }

    void* cnt_ptr = nullptr;
    cudaGetSymbolAddress(&cnt_ptr, g_cnt);
    float* g_ego_ptr = nullptr;
    { void* tmp = nullptr; cudaGetSymbolAddress(&tmp, g_ego); g_ego_ptr = (float*)tmp; }

    cudaMemsetAsync(cnt_ptr, 0, NTOT * sizeof(int));
    scatter_kernel<<<(NNZE + 255) / 256, 256>>>(val, row, col, ke0, ke1);

    for (int k = 0; k < NLAY; k++) {
        const float* eu = (k == 0) ? user_emb : g_ego_ptr;
        const float* ei = (k == 0) ? item_emb : g_ego_ptr + (size_t)UNUM * DIM;
        spmm_kernel<<<((NTOT / 2) * 32 + 255) / 256, 256>>>(eu, ei, mk0[k], mk1[k], k);
        combine_kernel<<<(NTOT + RPB - 1) / RPB, 256, SMEM>>>(
            W_gc + k * 4096, b_gc + k * 64, W_bi + k * 4096, b_bi + k * 64,
            eu, ei, k, (k != NLAY - 1) ? 1 : 0);
    }

    loss_kernel<<<(BSZ * 32 + 255) / 256, 256>>>(user_emb, item_emb, uid, pid, nid);
    fin_kernel<<<1, 1>>>((float*)d_out, out_size);
}